// round 1
// baseline (speedup 1.0000x reference)
#include <cuda_runtime.h>

// GaussianAdapter: smooth[b,r,f] = sum_t(dist*v)/sum_t(dist),
// dist = exp(-alpha*(ref[b,r]-ts[b,t,f])^2)*(ts>0) + 1e-7
// Shapes: B=16, T=512, R=128, F=32 (fixed by the dataset).

#define Bc 16
#define Tc 512
#define Rc 128
#define Fc 32
#define RT 4      // r values per block
#define TG 8      // t-groups (warps-worth) per block

__global__ __launch_bounds__(TG * Fc) void gaussian_adapter_kernel(
    const float* __restrict__ ts,     // [B,T,F]
    const float* __restrict__ vals,   // [B,T,F]
    const float* __restrict__ ref,    // [B,R]
    const float* __restrict__ alpha,  // [1]
    float* __restrict__ out)          // [B,R,F]
{
    const int b  = blockIdx.y;
    const int r0 = blockIdx.x * RT;
    const int f  = threadIdx.x & (Fc - 1);
    const int tg = threadIdx.x >> 5;

    const float a = alpha[0];
    const float c = -a * 1.44269504088896340736f;  // -alpha * log2(e)

    float rv[RT];
#pragma unroll
    for (int i = 0; i < RT; i++) rv[i] = ref[b * Rc + r0 + i];

    float num[RT], den[RT];
#pragma unroll
    for (int i = 0; i < RT; i++) { num[i] = 0.f; den[i] = 0.f; }

    const float* tsb = ts   + (size_t)b * Tc * Fc + f;
    const float* vb  = vals + (size_t)b * Tc * Fc + f;

#pragma unroll 4
    for (int t = tg; t < Tc; t += TG) {
        const float tv = __ldg(tsb + t * Fc);
        const float vv = __ldg(vb  + t * Fc);
        const float m  = (tv > 0.f) ? 1.f : 0.f;
#pragma unroll
        for (int i = 0; i < RT; i++) {
            const float d = rv[i] - tv;
            const float x = (c * d) * d;
            float w;
            asm("ex2.approx.ftz.f32 %0, %1;" : "=f"(w) : "f"(x));
            const float dist = fmaf(w, m, 1e-7f);
            den[i] += dist;
            num[i]  = fmaf(dist, vv, num[i]);
        }
    }

    // Reduce the TG t-groups per (r,f)
    __shared__ float sn[TG][RT][Fc];
    __shared__ float sd[TG][RT][Fc];
#pragma unroll
    for (int i = 0; i < RT; i++) {
        sn[tg][i][f] = num[i];
        sd[tg][i][f] = den[i];
    }
    __syncthreads();

    if (threadIdx.x < RT * Fc) {
        const int ri = threadIdx.x >> 5;  // which r within tile
        float n = 0.f, d = 0.f;
#pragma unroll
        for (int g = 0; g < TG; g++) {
            n += sn[g][ri][f];
            d += sd[g][ri][f];
        }
        out[(size_t)b * Rc * Fc + (r0 + ri) * Fc + f] = n / d;
    }
}

extern "C" void kernel_launch(void* const* d_in, const int* in_sizes, int n_in,
                              void* d_out, int out_size) {
    const float* ts    = (const float*)d_in[0];
    const float* vals  = (const float*)d_in[1];
    const float* ref   = (const float*)d_in[2];
    const float* alpha = (const float*)d_in[3];
    float* out = (float*)d_out;

    dim3 grid(Rc / RT, Bc);
    dim3 block(TG * Fc);
    gaussian_adapter_kernel<<<grid, block>>>(ts, vals, ref, alpha, out);
}

// round 4
// speedup vs baseline: 1.5251x; 1.5251x over previous
#include <cuda_runtime.h>

// GaussianAdapter: smooth[b,r,f] = sum_t(dist*v)/sum_t(dist),
// dist = exp(-alpha*(ref[b,r]-ts[b,t,f])^2)*(ts>0) + 1e-7
// Shapes: B=16, T=512, R=128, F=32 (fixed by the dataset).
//
// Algebra: with c = -alpha*log2(e),
//   exp(-a(r-t)^2) = 2^(c r^2) * 2^(s r + u),  s = -2 c t, u = c t^2
// E[r]=2^(c r^2) is t-invariant -> accumulate unscaled sums, apply E + eps
// corrections in the epilogue. Mask handled by substituting t<-1e3 when t<=0
// (drives w to exactly 0).

#define Bc 16
#define Tc 512
#define Rc 128
#define Fc 32
#define RT 4      // r values per block
#define TG 16     // t-groups (warps) per block
#define EPSF 1e-7f

__global__ __launch_bounds__(TG * Fc) void gaussian_adapter_kernel(
    const float* __restrict__ ts,     // [B,T,F]
    const float* __restrict__ vals,   // [B,T,F]
    const float* __restrict__ ref,    // [B,R]
    const float* __restrict__ alpha,  // [1]
    float* __restrict__ out)          // [B,R,F]
{
    const int b  = blockIdx.y;
    const int r0 = blockIdx.x * RT;
    const int f  = threadIdx.x & (Fc - 1);
    const int tg = threadIdx.x >> 5;

    const float a = alpha[0];
    const float c = -a * 1.44269504088896340736f;  // -alpha * log2(e)

    float rv[RT];
#pragma unroll
    for (int i = 0; i < RT; i++) rv[i] = __ldg(&ref[b * Rc + r0 + i]);

    float num[RT], den[RT];
#pragma unroll
    for (int i = 0; i < RT; i++) { num[i] = 0.f; den[i] = 0.f; }
    float sv = 0.f;  // sum of v over this warp's t-slice (for eps term)

    const float* tsb = ts   + (size_t)b * Tc * Fc + f;
    const float* vb  = vals + (size_t)b * Tc * Fc + f;

#pragma unroll 4
    for (int t = tg; t < Tc; t += TG) {
        const float tv = __ldg(tsb + t * Fc);
        const float vv = __ldg(vb  + t * Fc);
        const float tvm = (tv > 0.f) ? tv : 1.0e3f;  // masked t -> w==0
        const float ct  = c * tvm;
        const float u   = ct * tvm;      // c t^2
        const float s   = -2.0f * ct;    // -2 c t
        sv += vv;
#pragma unroll
        for (int i = 0; i < RT; i++) {
            const float y = fmaf(s, rv[i], u);
            float w;
            asm("ex2.approx.ftz.f32 %0, %1;" : "=f"(w) : "f"(y));
            den[i] += w;
            num[i]  = fmaf(w, vv, num[i]);
        }
    }

    // Reduce the TG t-groups per (r,f)
    __shared__ float sn[TG][RT][Fc];
    __shared__ float sd[TG][RT][Fc];
    __shared__ float ssv[TG][Fc];
#pragma unroll
    for (int i = 0; i < RT; i++) {
        sn[tg][i][f] = num[i];
        sd[tg][i][f] = den[i];
    }
    ssv[tg][f] = sv;
    __syncthreads();

    if (threadIdx.x < RT * Fc) {
        const int ri = threadIdx.x >> 5;  // which r within tile
        float n = 0.f, d = 0.f, svt = 0.f;
#pragma unroll
        for (int g = 0; g < TG; g++) {
            n   += sn[g][ri][f];
            d   += sd[g][ri][f];
            svt += ssv[g][f];
        }
        const float rr = __ldg(&ref[b * Rc + r0 + ri]);
        float E;
        const float ce = c * rr * rr;
        asm("ex2.approx.ftz.f32 %0, %1;" : "=f"(E) : "f"(ce));
        const float den_t = fmaf(E, d, (float)Tc * EPSF);
        const float num_t = fmaf(E, n, EPSF * svt);
        out[(size_t)b * Rc * Fc + (r0 + ri) * Fc + f] = num_t / den_t;
    }
}

extern "C" void kernel_launch(void* const* d_in, const int* in_sizes, int n_in,
                              void* d_out, int out_size) {
    const float* ts    = (const float*)d_in[0];
    const float* vals  = (const float*)d_in[1];
    const float* ref   = (const float*)d_in[2];
    const float* alpha = (const float*)d_in[3];
    float* out = (float*)d_out;

    dim3 grid(Rc / RT, Bc);
    dim3 block(TG * Fc);
    gaussian_adapter_kernel<<<grid, block>>>(ts, vals, ref, alpha, out);
}

// round 5
// speedup vs baseline: 1.7273x; 1.1326x over previous
#include <cuda_runtime.h>

// GaussianAdapter: smooth[b,r,f] = sum_t(dist*v)/sum_t(dist),
// dist = exp(-alpha*(ref[b,r]-ts[b,t,f])^2)*(ts>0) + 1e-7
// Shapes: B=16, T=512, R=128, F=32 (fixed by the dataset).
//
// Algebra: with c = -alpha*log2(e),
//   exp(-a(r-t)^2) = 2^(c r^2) * 2^(s r + u),  s = -2 c t, u = c t^2
// E[r]=2^(c r^2) is t-invariant -> accumulate unscaled sums, apply E + eps
// corrections in the epilogue. Mask handled by substituting t<-1e3 when t<=0
// (drives w to exactly 0). Inner math uses packed f32x2 (FFMA2/FADD2) to
// halve fma-pipe issue slots; MUFU EX2 is the remaining floor.

#define Bc 16
#define Tc 512
#define Rc 128
#define Fc 32
#define RT 4      // r values per block (2 f32x2 pairs)
#define TG 16     // t-groups (warps) per block
#define EPSF 1e-7f

typedef unsigned long long u64;

__device__ __forceinline__ u64 pk2(float lo, float hi) {
    u64 p;
    asm("mov.b64 %0, {%1,%2};" : "=l"(p)
        : "r"(__float_as_uint(lo)), "r"(__float_as_uint(hi)));
    return p;
}
__device__ __forceinline__ void upk2(u64 p, float& lo, float& hi) {
    unsigned int a, b;
    asm("mov.b64 {%0,%1}, %2;" : "=r"(a), "=r"(b) : "l"(p));
    lo = __uint_as_float(a); hi = __uint_as_float(b);
}
__device__ __forceinline__ u64 fma2(u64 a, u64 b, u64 c) {
    u64 d;
    asm("fma.rn.f32x2 %0, %1, %2, %3;" : "=l"(d) : "l"(a), "l"(b), "l"(c));
    return d;
}
__device__ __forceinline__ u64 add2(u64 a, u64 b) {
    u64 d;
    asm("add.rn.f32x2 %0, %1, %2;" : "=l"(d) : "l"(a), "l"(b));
    return d;
}
__device__ __forceinline__ float ex2f(float x) {
    float w;
    asm("ex2.approx.ftz.f32 %0, %1;" : "=f"(w) : "f"(x));
    return w;
}

__global__ __launch_bounds__(TG * Fc) void gaussian_adapter_kernel(
    const float* __restrict__ ts,     // [B,T,F]
    const float* __restrict__ vals,   // [B,T,F]
    const float* __restrict__ ref,    // [B,R]
    const float* __restrict__ alpha,  // [1]
    float* __restrict__ out)          // [B,R,F]
{
    const int b  = blockIdx.y;
    const int r0 = blockIdx.x * RT;
    const int f  = threadIdx.x & (Fc - 1);
    const int tg = threadIdx.x >> 5;

    const float a = alpha[0];
    const float c = -a * 1.44269504088896340736f;  // -alpha * log2(e)

    float rv[RT];
#pragma unroll
    for (int i = 0; i < RT; i++) rv[i] = __ldg(&ref[b * Rc + r0 + i]);
    const u64 rv01 = pk2(rv[0], rv[1]);
    const u64 rv23 = pk2(rv[2], rv[3]);

    u64 n01 = 0ull, n23 = 0ull, d01 = 0ull, d23 = 0ull;
    float sv = 0.f;  // sum of v over this warp's t-slice (for eps term)

    const float* tsb = ts   + (size_t)b * Tc * Fc + f;
    const float* vb  = vals + (size_t)b * Tc * Fc + f;

#pragma unroll 8
    for (int t = tg; t < Tc; t += TG) {
        const float tv = __ldg(tsb + t * Fc);
        const float vv = __ldg(vb  + t * Fc);
        const float tvm = (tv > 0.f) ? tv : 1.0e3f;  // masked t -> w==0
        const float ct  = c * tvm;
        const float u   = ct * tvm;       // c t^2
        const float s   = -(ct + ct);     // -2 c t
        sv += vv;

        const u64 s2 = pk2(s, s);
        const u64 u2 = pk2(u, u);
        const u64 v2 = pk2(vv, vv);

        const u64 y01 = fma2(s2, rv01, u2);
        const u64 y23 = fma2(s2, rv23, u2);

        float y0, y1, y2, y3;
        upk2(y01, y0, y1);
        upk2(y23, y2, y3);
        const u64 w01 = pk2(ex2f(y0), ex2f(y1));
        const u64 w23 = pk2(ex2f(y2), ex2f(y3));

        d01 = add2(d01, w01);
        d23 = add2(d23, w23);
        n01 = fma2(w01, v2, n01);
        n23 = fma2(w23, v2, n23);
    }

    // Reduce the TG t-groups per (r,f)
    __shared__ float sn[TG][RT][Fc];
    __shared__ float sd[TG][RT][Fc];
    __shared__ float ssv[TG][Fc];
    {
        float x0, x1;
        upk2(n01, x0, x1); sn[tg][0][f] = x0; sn[tg][1][f] = x1;
        upk2(n23, x0, x1); sn[tg][2][f] = x0; sn[tg][3][f] = x1;
        upk2(d01, x0, x1); sd[tg][0][f] = x0; sd[tg][1][f] = x1;
        upk2(d23, x0, x1); sd[tg][2][f] = x0; sd[tg][3][f] = x1;
        ssv[tg][f] = sv;
    }
    __syncthreads();

    if (threadIdx.x < RT * Fc) {
        const int ri = threadIdx.x >> 5;  // which r within tile
        float n = 0.f, d = 0.f, svt = 0.f;
#pragma unroll
        for (int g = 0; g < TG; g++) {
            n   += sn[g][ri][f];
            d   += sd[g][ri][f];
            svt += ssv[g][f];
        }
        const float rr = __ldg(&ref[b * Rc + r0 + ri]);
        const float E  = ex2f(c * rr * rr);
        const float den_t = fmaf(E, d, (float)Tc * EPSF);
        const float num_t = fmaf(E, n, EPSF * svt);
        out[(size_t)b * Rc * Fc + (r0 + ri) * Fc + f] = num_t / den_t;
    }
}

extern "C" void kernel_launch(void* const* d_in, const int* in_sizes, int n_in,
                              void* d_out, int out_size) {
    const float* ts    = (const float*)d_in[0];
    const float* vals  = (const float*)d_in[1];
    const float* ref   = (const float*)d_in[2];
    const float* alpha = (const float*)d_in[3];
    float* out = (float*)d_out;

    dim3 grid(Rc / RT, Bc);
    dim3 block(TG * Fc);
    gaussian_adapter_kernel<<<grid, block>>>(ts, vals, ref, alpha, out);
}

// round 8
// speedup vs baseline: 1.9404x; 1.1234x over previous
#include <cuda_runtime.h>

// GaussianAdapter: smooth[b,r,f] = sum_t(dist*v)/sum_t(dist),
// dist = exp(-alpha*(ref[b,r]-ts[b,t,f])^2)*(ts>0) + 1e-7
// Shapes: B=16, T=512, R=128, F=32 (fixed by the dataset).
//
// Algebra: with c = -alpha*log2(e),
//   exp(-a(r-t)^2) = 2^(c r^2) * 2^(s r + u),  s = -2 c t, u = c t^2
// E[r]=2^(c r^2) is t-invariant -> unscaled accumulation + epilogue fixup.
// Mask via t<-1e3 substitution (w==0 exactly). Packed f32x2 FMA/ADD.
// Loads are software-pipelined (register double buffer, 8-deep batches)
// to kill the L2-latency convoy stalls seen in round 5.

#define Bc 16
#define Tc 512
#define Rc 128
#define Fc 32
#define RT 4      // r values per block (2 f32x2 pairs)
#define TG 8      // warps per block
#define NB 8      // t-batches per warp
#define BL 8      // t's per batch  (TG*NB*BL == Tc)
#define EPSF 1e-7f

typedef unsigned long long u64;

__device__ __forceinline__ u64 pk2(float lo, float hi) {
    u64 p;
    asm("mov.b64 %0, {%1,%2};" : "=l"(p)
        : "r"(__float_as_uint(lo)), "r"(__float_as_uint(hi)));
    return p;
}
__device__ __forceinline__ void upk2(u64 p, float& lo, float& hi) {
    unsigned int a, b;
    asm("mov.b64 {%0,%1}, %2;" : "=r"(a), "=r"(b) : "l"(p));
    lo = __uint_as_float(a); hi = __uint_as_float(b);
}
__device__ __forceinline__ u64 fma2(u64 a, u64 b, u64 c) {
    u64 d;
    asm("fma.rn.f32x2 %0, %1, %2, %3;" : "=l"(d) : "l"(a), "l"(b), "l"(c));
    return d;
}
__device__ __forceinline__ u64 add2(u64 a, u64 b) {
    u64 d;
    asm("add.rn.f32x2 %0, %1, %2;" : "=l"(d) : "l"(a), "l"(b));
    return d;
}
__device__ __forceinline__ float ex2f(float x) {
    float w;
    asm("ex2.approx.ftz.f32 %0, %1;" : "=f"(w) : "f"(x));
    return w;
}

__global__ __launch_bounds__(TG * Fc, 4) void gaussian_adapter_kernel(
    const float* __restrict__ ts,     // [B,T,F]
    const float* __restrict__ vals,   // [B,T,F]
    const float* __restrict__ ref,    // [B,R]
    const float* __restrict__ alpha,  // [1]
    float* __restrict__ out)          // [B,R,F]
{
    const int b  = blockIdx.y;
    const int r0 = blockIdx.x * RT;
    const int f  = threadIdx.x & (Fc - 1);
    const int tg = threadIdx.x >> 5;

    const float a = alpha[0];
    const float c = -a * 1.44269504088896340736f;  // -alpha * log2(e)

    float rv[RT];
#pragma unroll
    for (int i = 0; i < RT; i++) rv[i] = __ldg(&ref[b * Rc + r0 + i]);
    const u64 rv01 = pk2(rv[0], rv[1]);
    const u64 rv23 = pk2(rv[2], rv[3]);

    u64 n01 = 0ull, n23 = 0ull, d01 = 0ull, d23 = 0ull;
    float sv = 0.f;  // sum of v over this warp's t-slice (for eps term)

    // Warp's t's: t = tg + 8*(batch*BL + j), batch=0..NB-1, j=0..BL-1
    const float* tsb = ts   + (size_t)b * Tc * Fc + (size_t)tg * Fc + f;
    const float* vb  = vals + (size_t)b * Tc * Fc + (size_t)tg * Fc + f;
    // stride between consecutive t's of this warp: TG*Fc floats
    const int STRD = TG * Fc;

    float tbuf[2][BL], vbuf[2][BL];

    // prologue: load batch 0
#pragma unroll
    for (int j = 0; j < BL; j++) {
        tbuf[0][j] = __ldg(tsb + j * STRD);
        vbuf[0][j] = __ldg(vb  + j * STRD);
    }

#pragma unroll
    for (int batch = 0; batch < NB; batch++) {
        const int cur = batch & 1;
        const int nxt = cur ^ 1;
        // prefetch next batch first (overlaps with compute below)
        if (batch + 1 < NB) {
            const int base = (batch + 1) * BL;
#pragma unroll
            for (int j = 0; j < BL; j++) {
                tbuf[nxt][j] = __ldg(tsb + (base + j) * STRD);
                vbuf[nxt][j] = __ldg(vb  + (base + j) * STRD);
            }
        }
#pragma unroll
        for (int j = 0; j < BL; j++) {
            const float tv  = tbuf[cur][j];
            const float vv  = vbuf[cur][j];
            const float tvm = (tv > 0.f) ? tv : 1.0e3f;  // masked t -> w==0
            const float ct  = c * tvm;
            const float u   = ct * tvm;       // c t^2
            const float s   = -(ct + ct);     // -2 c t
            sv += vv;

            const u64 s2 = pk2(s, s);
            const u64 u2 = pk2(u, u);
            const u64 v2 = pk2(vv, vv);

            const u64 y01 = fma2(s2, rv01, u2);
            const u64 y23 = fma2(s2, rv23, u2);

            float y0, y1, y2, y3;
            upk2(y01, y0, y1);
            upk2(y23, y2, y3);
            const u64 w01 = pk2(ex2f(y0), ex2f(y1));
            const u64 w23 = pk2(ex2f(y2), ex2f(y3));

            d01 = add2(d01, w01);
            d23 = add2(d23, w23);
            n01 = fma2(w01, v2, n01);
            n23 = fma2(w23, v2, n23);
        }
    }

    // Reduce the TG t-groups per (r,f)
    __shared__ float sn[TG][RT][Fc];
    __shared__ float sd[TG][RT][Fc];
    __shared__ float ssv[TG][Fc];
    {
        float x0, x1;
        upk2(n01, x0, x1); sn[tg][0][f] = x0; sn[tg][1][f] = x1;
        upk2(n23, x0, x1); sn[tg][2][f] = x0; sn[tg][3][f] = x1;
        upk2(d01, x0, x1); sd[tg][0][f] = x0; sd[tg][1][f] = x1;
        upk2(d23, x0, x1); sd[tg][2][f] = x0; sd[tg][3][f] = x1;
        ssv[tg][f] = sv;
    }
    __syncthreads();

    if (threadIdx.x < RT * Fc) {
        const int ri = threadIdx.x >> 5;  // which r within tile
        float n = 0.f, d = 0.f, svt = 0.f;
#pragma unroll
        for (int g = 0; g < TG; g++) {
            n   += sn[g][ri][f];
            d   += sd[g][ri][f];
            svt += ssv[g][f];
        }
        const float rr = __ldg(&ref[b * Rc + r0 + ri]);
        const float E  = ex2f(c * rr * rr);
        const float den_t = fmaf(E, d, (float)Tc * EPSF);
        const float num_t = fmaf(E, n, EPSF * svt);
        out[(size_t)b * Rc * Fc + (r0 + ri) * Fc + f] = num_t / den_t;
    }
}

extern "C" void kernel_launch(void* const* d_in, const int* in_sizes, int n_in,
                              void* d_out, int out_size) {
    const float* ts    = (const float*)d_in[0];
    const float* vals  = (const float*)d_in[1];
    const float* ref   = (const float*)d_in[2];
    const float* alpha = (const float*)d_in[3];
    float* out = (float*)d_out;

    dim3 grid(Rc / RT, Bc);
    dim3 block(TG * Fc);
    gaussian_adapter_kernel<<<grid, block>>>(ts, vals, ref, alpha, out);
}

// round 9
// speedup vs baseline: 2.2800x; 1.1750x over previous
#include <cuda_runtime.h>

// GaussianAdapter: smooth[b,r,f] = sum_t(dist*v)/sum_t(dist),
// dist = exp(-alpha*(ref[b,r]-ts[b,t,f])^2)*(ts>0) + 1e-7
// Shapes: B=16, T=512, R=128, F=32 (fixed by the dataset).
//
// Algebra: with c = -alpha*log2(e),
//   exp(-a(r-t)^2) = 2^(c r^2) * 2^(ct*(-2 r) + c t^2)
// E[r]=2^(c r^2) is t-invariant -> unscaled accumulation + epilogue fixup.
// Mask via t<-1e3 substitution (w==0 exactly). Packed f32x2 over r-pairs.
// RT=8 amortizes per-t overhead (issue ~5/ (t,r) vs 8 MUFU-cyc -> MUFU-bound).
// 256 blocks x 512 threads = single wave on 148 SMs.

#define Bc 16
#define Tc 512
#define Rc 128
#define Fc 32
#define RT 8      // r values per block (4 f32x2 pairs)
#define TG 16     // warps per block
#define NB 8      // t-batches per warp
#define BL 4      // t's per batch  (TG*NB*BL == Tc)
#define EPSF 1e-7f

typedef unsigned long long u64;

__device__ __forceinline__ u64 pk2(float lo, float hi) {
    u64 p;
    asm("mov.b64 %0, {%1,%2};" : "=l"(p)
        : "r"(__float_as_uint(lo)), "r"(__float_as_uint(hi)));
    return p;
}
__device__ __forceinline__ void upk2(u64 p, float& lo, float& hi) {
    unsigned int a, b;
    asm("mov.b64 {%0,%1}, %2;" : "=r"(a), "=r"(b) : "l"(p));
    lo = __uint_as_float(a); hi = __uint_as_float(b);
}
__device__ __forceinline__ u64 fma2(u64 a, u64 b, u64 c) {
    u64 d;
    asm("fma.rn.f32x2 %0, %1, %2, %3;" : "=l"(d) : "l"(a), "l"(b), "l"(c));
    return d;
}
__device__ __forceinline__ u64 add2(u64 a, u64 b) {
    u64 d;
    asm("add.rn.f32x2 %0, %1, %2;" : "=l"(d) : "l"(a), "l"(b));
    return d;
}
__device__ __forceinline__ float ex2f(float x) {
    float w;
    asm("ex2.approx.ftz.f32 %0, %1;" : "=f"(w) : "f"(x));
    return w;
}

__global__ __launch_bounds__(TG * Fc, 2) void gaussian_adapter_kernel(
    const float* __restrict__ ts,     // [B,T,F]
    const float* __restrict__ vals,   // [B,T,F]
    const float* __restrict__ ref,    // [B,R]
    const float* __restrict__ alpha,  // [1]
    float* __restrict__ out)          // [B,R,F]
{
    const int b  = blockIdx.y;
    const int r0 = blockIdx.x * RT;
    const int f  = threadIdx.x & (Fc - 1);
    const int tg = threadIdx.x >> 5;

    const float a = alpha[0];
    const float c = -a * 1.44269504088896340736f;  // -alpha * log2(e)

    // rn[i] = -2 * r_i, packed in pairs (loop-invariant multiplier of ct)
    u64 rn[RT / 2];
#pragma unroll
    for (int i = 0; i < RT / 2; i++) {
        const float ra = __ldg(&ref[b * Rc + r0 + 2 * i]);
        const float rb = __ldg(&ref[b * Rc + r0 + 2 * i + 1]);
        rn[i] = pk2(-2.0f * ra, -2.0f * rb);
    }

    u64 num[RT / 2], den[RT / 2];
#pragma unroll
    for (int i = 0; i < RT / 2; i++) { num[i] = 0ull; den[i] = 0ull; }
    float sv = 0.f;  // sum of v over this warp's t-slice (for eps term)

    const float* tsb = ts   + (size_t)b * Tc * Fc + (size_t)tg * Fc + f;
    const float* vb  = vals + (size_t)b * Tc * Fc + (size_t)tg * Fc + f;
    const int STRD = TG * Fc;  // stride between this warp's consecutive t's

    float tbuf[2][BL], vbuf[2][BL];

    // prologue: load batch 0
#pragma unroll
    for (int j = 0; j < BL; j++) {
        tbuf[0][j] = __ldg(tsb + j * STRD);
        vbuf[0][j] = __ldg(vb  + j * STRD);
    }

#pragma unroll
    for (int batch = 0; batch < NB; batch++) {
        const int cur = batch & 1;
        const int nxt = cur ^ 1;
        if (batch + 1 < NB) {
            const int base = (batch + 1) * BL;
#pragma unroll
            for (int j = 0; j < BL; j++) {
                tbuf[nxt][j] = __ldg(tsb + (base + j) * STRD);
                vbuf[nxt][j] = __ldg(vb  + (base + j) * STRD);
            }
        }
#pragma unroll
        for (int j = 0; j < BL; j++) {
            const float tv  = tbuf[cur][j];
            const float vv  = vbuf[cur][j];
            const float tvm = (tv > 0.f) ? tv : 1.0e3f;  // masked t -> w==0
            const float ct  = c * tvm;
            const float u   = ct * tvm;       // c t^2
            sv += vv;

            const u64 ct2 = pk2(ct, ct);
            const u64 u2  = pk2(u, u);
            const u64 v2  = pk2(vv, vv);

#pragma unroll
            for (int i = 0; i < RT / 2; i++) {
                const u64 y2 = fma2(ct2, rn[i], u2);  // ct*(-2r) + c t^2
                float y0, y1;
                upk2(y2, y0, y1);
                const u64 w2 = pk2(ex2f(y0), ex2f(y1));
                den[i] = add2(den[i], w2);
                num[i] = fma2(w2, v2, num[i]);
            }
        }
    }

    // Reduce the TG t-groups per (r,f)
    __shared__ float sn[TG][RT][Fc];
    __shared__ float sd[TG][RT][Fc];
    __shared__ float ssv[TG][Fc];
#pragma unroll
    for (int i = 0; i < RT / 2; i++) {
        float x0, x1;
        upk2(num[i], x0, x1); sn[tg][2 * i][f] = x0; sn[tg][2 * i + 1][f] = x1;
        upk2(den[i], x0, x1); sd[tg][2 * i][f] = x0; sd[tg][2 * i + 1][f] = x1;
    }
    ssv[tg][f] = sv;
    __syncthreads();

    if (threadIdx.x < RT * Fc) {
        const int ri = threadIdx.x >> 5;  // which r within tile
        float n = 0.f, d = 0.f, svt = 0.f;
#pragma unroll
        for (int g = 0; g < TG; g++) {
            n   += sn[g][ri][f];
            d   += sd[g][ri][f];
            svt += ssv[g][f];
        }
        const float rr = __ldg(&ref[b * Rc + r0 + ri]);
        const float E  = ex2f(c * rr * rr);
        const float den_t = fmaf(E, d, (float)Tc * EPSF);
        const float num_t = fmaf(E, n, EPSF * svt);
        out[(size_t)b * Rc * Fc + (r0 + ri) * Fc + f] = num_t / den_t;
    }
}

extern "C" void kernel_launch(void* const* d_in, const int* in_sizes, int n_in,
                              void* d_out, int out_size) {
    const float* ts    = (const float*)d_in[0];
    const float* vals  = (const float*)d_in[1];
    const float* ref   = (const float*)d_in[2];
    const float* alpha = (const float*)d_in[3];
    float* out = (float*)d_out;

    dim3 grid(Rc / RT, Bc);
    dim3 block(TG * Fc);
    gaussian_adapter_kernel<<<grid, block>>>(ts, vals, ref, alpha, out);
}